// round 5
// baseline (speedup 1.0000x reference)
#include <cuda_runtime.h>
#include <cuda_bf16.h>

// ANFIS fused kernel for GB300 (sm_103a) — round 4.
//
//   e0[b,i]=exp(-((x0-mean0_i)/sig0_i)^2), e1[b,j]=..., S[b]=sum(e0)*sum(e1)
//   G_k[b,i] = sum_j e1[b,j] * A_k[i,j],  A = {cw0, cw1, cb}
//   out[b] = ( sum_i e0[b,i]*(x0*G0 + x1*G1 + G2) ) / S[b]
//
// R4: rule kernel is a pure 3-matrix GEMM, f32x2 packed over j (both FMA2
// operands are natural 8B loads, zero dup-pack movs). Normalization deferred.

#define M_MF 512
#define B_SZ 256
#define TIB  32              // i-rows per block
#define TBB  32              // batches per block
#define JSPL 4               // K-splits
#define KSP  (M_MF / JSPL)   // 128 j per block
#define NIT  (M_MF / TIB)    // 16 i-tiles
#define NBT  (B_SZ / TBB)    // 8 b-tiles
#define NPART (NIT * JSPL)   // 64 partials per batch

__device__ float g_cw0[M_MF * M_MF];
__device__ float g_cw1[M_MF * M_MF];
__device__ float g_e0[B_SZ * M_MF];
__device__ float g_e1[B_SZ * M_MF];
__device__ float g_S[B_SZ];
__device__ float g_scratch[B_SZ * NPART];

typedef unsigned long long u64;

__device__ __forceinline__ u64 fma2(u64 a, u64 b, u64 c) {
    u64 r; asm("fma.rn.f32x2 %0, %1, %2, %3;" : "=l"(r) : "l"(a), "l"(b), "l"(c)); return r;
}
__device__ __forceinline__ void unpack2(u64 a, float& lo, float& hi) {
    asm("mov.b64 {%0, %1}, %2;" : "=f"(lo), "=f"(hi) : "l"(a));
}

// ---------------------------------------------------------------------------
// Kernel 1: membership (unnormalized) + S products + cw de-interleave.
// One block per batch, 512 threads.
// ---------------------------------------------------------------------------
__global__ void __launch_bounds__(M_MF) memb_kernel(
    const float* __restrict__ x,
    const float* __restrict__ mean,
    const float* __restrict__ sigma,
    const float* __restrict__ cw)
{
    // De-interleave cw [R,2] -> g_cw0, g_cw1 (grid-stride over all threads).
    {
        const float2* __restrict__ cw2 = (const float2*)cw;
        int gtid = blockIdx.x * M_MF + threadIdx.x;          // 131072 threads
        #pragma unroll
        for (int r = gtid; r < M_MF * M_MF; r += B_SZ * M_MF) {
            float2 v = cw2[r];
            g_cw0[r] = v.x;
            g_cw1[r] = v.y;
        }
    }

    __shared__ float s0[16], s1[16];
    const int b    = blockIdx.x;
    const int m    = threadIdx.x;
    const int lane = m & 31;
    const int wrp  = m >> 5;

    const float x0 = x[b * 2 + 0];
    const float x1 = x[b * 2 + 1];

    const float d0 = (x0 - mean[m]) * __fdividef(1.0f, sigma[m]);
    const float e0 = __expf(-d0 * d0);
    const float d1 = (x1 - mean[M_MF + m]) * __fdividef(1.0f, sigma[M_MF + m]);
    const float e1 = __expf(-d1 * d1);

    float r0 = e0, r1 = e1;
    #pragma unroll
    for (int off = 16; off > 0; off >>= 1) {
        r0 += __shfl_down_sync(0xFFFFFFFFu, r0, off);
        r1 += __shfl_down_sync(0xFFFFFFFFu, r1, off);
    }
    if (lane == 0) { s0[wrp] = r0; s1[wrp] = r1; }
    __syncthreads();

    if (m < 32) {
        float v0 = (lane < 16) ? s0[lane] : 0.0f;
        float v1 = (lane < 16) ? s1[lane] : 0.0f;
        #pragma unroll
        for (int off = 8; off > 0; off >>= 1) {
            v0 += __shfl_down_sync(0xFFFFFFFFu, v0, off);
            v1 += __shfl_down_sync(0xFFFFFFFFu, v1, off);
        }
        if (lane == 0) g_S[b] = v0 * v1;
    }

    g_e0[b * M_MF + m] = e0;
    g_e1[b * M_MF + m] = e1;
}

// ---------------------------------------------------------------------------
// Kernel 2: 3-matrix GEMM, f32x2 packed over j.
// Grid (NIT, NBT, JSPL), 128 threads. Thread tile: 2 i-rows x 4 batches.
// Warp = 8 b-lanes x 4 i-threads -> A addresses dedup within warp.
// ---------------------------------------------------------------------------
__global__ void __launch_bounds__(128) rule_kernel(
    const float* __restrict__ x,
    const float* __restrict__ cb)
{
    const int tx = threadIdx.x & 7;        // b-thread 0..7
    const int ty = threadIdx.x >> 3;       // i-thread 0..15
    const int i0 = blockIdx.x * TIB + ty * 2;
    const int b0 = blockIdx.y * TBB + tx * 4;
    const int j0 = blockIdx.z * KSP;

    u64 acc[2][4][3];
    #pragma unroll
    for (int iL = 0; iL < 2; ++iL)
        #pragma unroll
        for (int bL = 0; bL < 4; ++bL)
            #pragma unroll
            for (int k = 0; k < 3; ++k)
                acc[iL][bL][k] = 0ull;

    #pragma unroll 2
    for (int s = 0; s < KSP / 2; ++s) {
        const int j = j0 + 2 * s;

        u64 a0[2], a1[2], ab[2];
        #pragma unroll
        for (int iL = 0; iL < 2; ++iL) {
            const int r = (i0 + iL) * M_MF + j;
            a0[iL] = *(const u64*)&g_cw0[r];
            a1[iL] = *(const u64*)&g_cw1[r];
            ab[iL] = *(const u64*)&cb[r];
        }
        u64 e1p[4];
        #pragma unroll
        for (int bL = 0; bL < 4; ++bL)
            e1p[bL] = *(const u64*)&g_e1[(b0 + bL) * M_MF + j];

        #pragma unroll
        for (int iL = 0; iL < 2; ++iL)
            #pragma unroll
            for (int bL = 0; bL < 4; ++bL) {
                acc[iL][bL][0] = fma2(a0[iL], e1p[bL], acc[iL][bL][0]);
                acc[iL][bL][1] = fma2(a1[iL], e1p[bL], acc[iL][bL][1]);
                acc[iL][bL][2] = fma2(ab[iL], e1p[bL], acc[iL][bL][2]);
            }
    }

    // Epilogue: combine with x and e0, reduce over i-threads (deterministic).
    float v[4];
    #pragma unroll
    for (int bL = 0; bL < 4; ++bL) {
        const int b   = b0 + bL;
        const float xv0 = x[b * 2 + 0];
        const float xv1 = x[b * 2 + 1];
        float acc_b = 0.0f;
        #pragma unroll
        for (int iL = 0; iL < 2; ++iL) {
            float g0l, g0h, g1l, g1h, g2l, g2h;
            unpack2(acc[iL][bL][0], g0l, g0h);
            unpack2(acc[iL][bL][1], g1l, g1h);
            unpack2(acc[iL][bL][2], g2l, g2h);
            const float g0 = g0l + g0h;
            const float g1 = g1l + g1h;
            const float g2 = g2l + g2h;
            const float h  = fmaf(xv0, g0, fmaf(xv1, g1, g2));
            acc_b = fmaf(g_e0[b * M_MF + i0 + iL], h, acc_b);
        }
        v[bL] = acc_b;
    }

    __shared__ float sred[16][TBB];
    #pragma unroll
    for (int bL = 0; bL < 4; ++bL)
        sred[ty][tx * 4 + bL] = v[bL];
    __syncthreads();

    if (threadIdx.x < TBB) {
        float s = 0.0f;
        #pragma unroll
        for (int t = 0; t < 16; ++t) s += sred[t][threadIdx.x];
        const int b = blockIdx.y * TBB + threadIdx.x;
        g_scratch[b * NPART + blockIdx.x * JSPL + blockIdx.z] = s;
    }
}

// ---------------------------------------------------------------------------
// Kernel 3: deterministic final sum + deferred normalization.
// ---------------------------------------------------------------------------
__global__ void __launch_bounds__(B_SZ) final_kernel(float* __restrict__ out)
{
    const int b = threadIdx.x;
    float s = 0.0f;
    #pragma unroll
    for (int p = 0; p < NPART; ++p) s += g_scratch[b * NPART + p];
    out[b] = s / g_S[b];
}

// ---------------------------------------------------------------------------
extern "C" void kernel_launch(void* const* d_in, const int* in_sizes, int n_in,
                              void* d_out, int out_size)
{
    const float* x     = (const float*)d_in[0];   // [B, 2]
    const float* mean  = (const float*)d_in[1];   // [2, M]
    const float* sigma = (const float*)d_in[2];   // [2, M]
    const float* cw    = (const float*)d_in[3];   // [R, 2]
    const float* cb    = (const float*)d_in[4];   // [R, 1]
    float* out = (float*)d_out;                   // [B, 1]

    memb_kernel<<<B_SZ, M_MF>>>(x, mean, sigma, cw);
    rule_kernel<<<dim3(NIT, NBT, JSPL), 128>>>(x, cb);
    final_kernel<<<1, B_SZ>>>(out);
}

// round 9
// speedup vs baseline: 2.3269x; 2.3269x over previous
#include <cuda_runtime.h>
#include <cuda_bf16.h>
#include <cstdint>

// ANFIS on GB300 — round 8: HMMA (mma.sync bf16) formulation.
// tcgen05 is unavailable: harness PTX target is compute_103 (no 'a'), so only
// base-ISA tensor ops (mma.sync / ldmatrix) assemble. They map to HMMA SASS.
//
//   e0[b,i], e1[b,j] raw memberships; S[b] = (sum e0)(sum e1)
//   D[b, n=(k,i)] = sum_j e1[b,j] * W_k[i,j]   (W_0=cw0, W_1=cw1, W_2=cb)
//   out[b] = sum_i e0[b,i]*(x0*D0 + x1*D1 + D2) / S[b]
// Precision: e1, W split bf16 hi+lo; 3 passes eh*Wh + el*Wh + eh*Wl, fp32 acc.

#define M_MF 512
#define B_SZ 256
#define NTOT 1536
#define CTA_M 64
#define CTA_N 128
#define KCH  64
#define KPAD 72                   // padded bf16 stride (LDSM conflict-free)
#define MT 4
#define NT 12
#define KS 2
#define NPART (NT * KS)           // 24
#define NCHUNK 12                 // 3 passes * (256/64)
#define A_STAGE (CTA_M * KPAD)    // bf16 elems
#define B_STAGE (CTA_N * KPAD)
#define STAGE_BYTES ((A_STAGE + B_STAGE) * 2)     // 27648
#define DSMEM_BYTES (2 * STAGE_BYTES)             // 55296

__device__ __align__(16) __nv_bfloat16 g_Bwh[NTOT * M_MF];
__device__ __align__(16) __nv_bfloat16 g_Bwl[NTOT * M_MF];
__device__ __align__(16) __nv_bfloat16 g_e1h[B_SZ * M_MF];
__device__ __align__(16) __nv_bfloat16 g_e1l[B_SZ * M_MF];
__device__ __align__(16) float g_e0[B_SZ * M_MF];
__device__ float g_S[B_SZ];
__device__ float g_part[B_SZ * NPART];

__device__ __forceinline__ uint32_t smem_u32(const void* p) {
    uint32_t a;
    asm("{ .reg .u64 t; cvta.to.shared.u64 t, %1; cvt.u32.u64 %0, t; }" : "=r"(a) : "l"(p));
    return a;
}
__device__ __forceinline__ void ldsm_x4(uint32_t& r0, uint32_t& r1, uint32_t& r2,
                                        uint32_t& r3, uint32_t addr) {
    asm volatile("ldmatrix.sync.aligned.m8n8.x4.shared.b16 {%0,%1,%2,%3}, [%4];"
                 : "=r"(r0), "=r"(r1), "=r"(r2), "=r"(r3) : "r"(addr));
}
__device__ __forceinline__ void mma16816(float* d, const uint32_t* a,
                                         uint32_t b0, uint32_t b1) {
    asm volatile(
        "mma.sync.aligned.m16n8k16.row.col.f32.bf16.bf16.f32 "
        "{%0,%1,%2,%3}, {%4,%5,%6,%7}, {%8,%9}, {%0,%1,%2,%3};"
        : "+f"(d[0]), "+f"(d[1]), "+f"(d[2]), "+f"(d[3])
        : "r"(a[0]), "r"(a[1]), "r"(a[2]), "r"(a[3]), "r"(b0), "r"(b1));
}
__device__ __forceinline__ uint32_t pack_bf2(__nv_bfloat16 a, __nv_bfloat16 b) {
    return (uint32_t)__bfloat16_as_ushort(a) | ((uint32_t)__bfloat16_as_ushort(b) << 16);
}

// ---------------------------------------------------------------------------
// Kernel 1 (prep): W hi/lo split (all 384 blocks) + membership (blocks 0-127).
// ---------------------------------------------------------------------------
__global__ void __launch_bounds__(512) prep_kernel(
    const float* __restrict__ x,
    const float* __restrict__ mean,
    const float* __restrict__ sigma,
    const float* __restrict__ cw,
    const float* __restrict__ cb)
{
    const int tid = threadIdx.x;
    const int bx  = blockIdx.x;

    {   // weight split: row n = 4*bx + tid/128, j = (tid%128)*4
        const int n = bx * 4 + (tid >> 7);
        const int j = (tid & 127) * 4;
        float v[4];
        if (n < 1024) {
            const int i = (n < 512) ? n : (n - 512);
            const float4* p = (const float4*)(cw + ((size_t)i * 512 + j) * 2);
            const float4 a = p[0], bq = p[1];
            if (n < 512) { v[0] = a.x; v[1] = a.z; v[2] = bq.x; v[3] = bq.z; }
            else         { v[0] = a.y; v[1] = a.w; v[2] = bq.y; v[3] = bq.w; }
        } else {
            const float4 a = *(const float4*)(cb + (size_t)(n - 1024) * 512 + j);
            v[0] = a.x; v[1] = a.y; v[2] = a.z; v[3] = a.w;
        }
        __nv_bfloat16 h[4], l[4];
        #pragma unroll
        for (int e = 0; e < 4; ++e) {
            h[e] = __float2bfloat16(v[e]);
            l[e] = __float2bfloat16(v[e] - __bfloat162float(h[e]));
        }
        const size_t o = (size_t)n * 512 + j;
        *(uint2*)&g_Bwh[o] = make_uint2(pack_bf2(h[0], h[1]), pack_bf2(h[2], h[3]));
        *(uint2*)&g_Bwl[o] = make_uint2(pack_bf2(l[0], l[1]), pack_bf2(l[2], l[3]));
    }

    if (bx < 128) {   // membership: 2 batches per block
        __shared__ float sm[16][4];
        const int m    = tid;
        const int lane = m & 31;
        const int wrp  = m >> 5;
        const int ba   = 2 * bx, bb = ba + 1;

        const float i0s = __fdividef(1.0f, sigma[m]);
        const float i1s = __fdividef(1.0f, sigma[512 + m]);
        const float mn0 = mean[m], mn1 = mean[512 + m];
        const float xa0 = x[2 * ba], xa1 = x[2 * ba + 1];
        const float xb0 = x[2 * bb], xb1 = x[2 * bb + 1];

        float d;
        d = (xa0 - mn0) * i0s;  const float e0a = __expf(-d * d);
        d = (xa1 - mn1) * i1s;  const float e1a = __expf(-d * d);
        d = (xb0 - mn0) * i0s;  const float e0b = __expf(-d * d);
        d = (xb1 - mn1) * i1s;  const float e1b = __expf(-d * d);

        float r0 = e0a, r1 = e1a, r2 = e0b, r3 = e1b;
        #pragma unroll
        for (int off = 16; off > 0; off >>= 1) {
            r0 += __shfl_down_sync(0xFFFFFFFFu, r0, off);
            r1 += __shfl_down_sync(0xFFFFFFFFu, r1, off);
            r2 += __shfl_down_sync(0xFFFFFFFFu, r2, off);
            r3 += __shfl_down_sync(0xFFFFFFFFu, r3, off);
        }
        if (lane == 0) { sm[wrp][0] = r0; sm[wrp][1] = r1; sm[wrp][2] = r2; sm[wrp][3] = r3; }
        __syncthreads();
        if (m < 32) {
            float v0 = (lane < 16) ? sm[lane][0] : 0.0f;
            float v1 = (lane < 16) ? sm[lane][1] : 0.0f;
            float v2 = (lane < 16) ? sm[lane][2] : 0.0f;
            float v3 = (lane < 16) ? sm[lane][3] : 0.0f;
            #pragma unroll
            for (int off = 8; off > 0; off >>= 1) {
                v0 += __shfl_down_sync(0xFFFFFFFFu, v0, off);
                v1 += __shfl_down_sync(0xFFFFFFFFu, v1, off);
                v2 += __shfl_down_sync(0xFFFFFFFFu, v2, off);
                v3 += __shfl_down_sync(0xFFFFFFFFu, v3, off);
            }
            if (lane == 0) { g_S[ba] = v0 * v1; g_S[bb] = v2 * v3; }
        }

        g_e0[(size_t)ba * 512 + m] = e0a;
        g_e0[(size_t)bb * 512 + m] = e0b;
        __nv_bfloat16 h;
        h = __float2bfloat16(e1a);
        g_e1h[(size_t)ba * 512 + m] = h;
        g_e1l[(size_t)ba * 512 + m] = __float2bfloat16(e1a - __bfloat162float(h));
        h = __float2bfloat16(e1b);
        g_e1h[(size_t)bb * 512 + m] = h;
        g_e1l[(size_t)bb * 512 + m] = __float2bfloat16(e1b - __bfloat162float(h));
    }
}

// ---------------------------------------------------------------------------
// Kernel 2: HMMA GEMM + epilogue. Grid (MT=4, NT=12, KS=2), 256 threads.
// CTA tile 64(b) x 128(n); warps 2(m) x 4(n), warp tile 32x32.
// ---------------------------------------------------------------------------
extern __shared__ __align__(16) char dynsmem[];

__global__ void __launch_bounds__(256) gemm_kernel(const float* __restrict__ x)
{
    const int tid   = threadIdx.x;
    const int lane  = tid & 31;
    const int wid   = tid >> 5;
    const int warpM = wid >> 2;          // 0..1
    const int warpN = wid & 3;           // 0..3
    const int mt = blockIdx.x, nt = blockIdx.y, ks = blockIdx.z;
    const int b0  = mt * CTA_M;
    const int n0g = nt * CTA_N;
    const int jbase = ks * (M_MF / KS);

    __nv_bfloat16* bufA[2] = { (__nv_bfloat16*)dynsmem,
                               (__nv_bfloat16*)(dynsmem + STAGE_BYTES) };
    __nv_bfloat16* bufB[2] = { bufA[0] + A_STAGE, bufA[1] + A_STAGE };

    float acc[2][4][4];
    #pragma unroll
    for (int mi = 0; mi < 2; ++mi)
        #pragma unroll
        for (int nf = 0; nf < 4; ++nf)
            #pragma unroll
            for (int e = 0; e < 4; ++e) acc[mi][nf][e] = 0.0f;

    // per-chunk gmem load into regs
    uint4 ra[2], rb[4];
    auto ldg_chunk = [&](int c) {
        const int pass = c >> 2;
        const int kc   = c & 3;
        const int j0   = jbase + kc * KCH;
        const __nv_bfloat16* As = (pass == 1) ? g_e1l : g_e1h;
        const __nv_bfloat16* Bs = (pass == 2) ? g_Bwl : g_Bwh;
        #pragma unroll
        for (int it = 0; it < 2; ++it) {
            const int idx = tid + it * 256;
            ra[it] = *(const uint4*)(As + (size_t)(b0 + (idx >> 3)) * 512 + j0 + (idx & 7) * 8);
        }
        #pragma unroll
        for (int it = 0; it < 4; ++it) {
            const int idx = tid + it * 256;
            rb[it] = *(const uint4*)(Bs + (size_t)(n0g + (idx >> 3)) * 512 + j0 + (idx & 7) * 8);
        }
    };
    auto sts_chunk = [&](int buf) {
        #pragma unroll
        for (int it = 0; it < 2; ++it) {
            const int idx = tid + it * 256;
            *(uint4*)(bufA[buf] + (idx >> 3) * KPAD + (idx & 7) * 8) = ra[it];
        }
        #pragma unroll
        for (int it = 0; it < 4; ++it) {
            const int idx = tid + it * 256;
            *(uint4*)(bufB[buf] + (idx >> 3) * KPAD + (idx & 7) * 8) = rb[it];
        }
    };

    // ldmatrix lane address components
    const int aRow = warpM * 32 + (lane & 15);          // + mi*16
    const int aCol = (lane >> 4) << 3;                  // + k0
    const int bRow = warpN * 32 + ((lane >> 4) << 3) + (lane & 7);  // + bi*16
    const int bCol = ((lane >> 3) & 1) << 3;            // + k0

    ldg_chunk(0);
    sts_chunk(0);
    __syncthreads();

    for (int c = 0; c < NCHUNK; ++c) {
        const int cur = c & 1;
        if (c + 1 < NCHUNK) ldg_chunk(c + 1);

        const uint32_t sA = smem_u32(bufA[cur]);
        const uint32_t sB = smem_u32(bufB[cur]);
        #pragma unroll
        for (int k16 = 0; k16 < KCH / 16; ++k16) {
            const int k0 = k16 * 16;
            uint32_t a[2][4];
            #pragma unroll
            for (int mi = 0; mi < 2; ++mi)
                ldsm_x4(a[mi][0], a[mi][1], a[mi][2], a[mi][3],
                        sA + (uint32_t)(((aRow + mi * 16) * KPAD + k0 + aCol) * 2));
            uint32_t bfr[4][2];
            #pragma unroll
            for (int bi = 0; bi < 2; ++bi) {
                uint32_t r0, r1, r2, r3;
                ldsm_x4(r0, r1, r2, r3,
                        sB + (uint32_t)(((bRow + bi * 16) * KPAD + k0 + bCol) * 2));
                bfr[bi * 2 + 0][0] = r0; bfr[bi * 2 + 0][1] = r1;
                bfr[bi * 2 + 1][0] = r2; bfr[bi * 2 + 1][1] = r3;
            }
            #pragma unroll
            for (int mi = 0; mi < 2; ++mi)
                #pragma unroll
                for (int nf = 0; nf < 4; ++nf)
                    mma16816(acc[mi][nf], a[mi], bfr[nf][0], bfr[nf][1]);
        }

        if (c + 1 < NCHUNK) sts_chunk(cur ^ 1);
        __syncthreads();
    }

    // ---- epilogue ----
    const int kmat = nt >> 2;                 // 0:cw0  1:cw1  2:cb
    const int i0   = (nt & 3) * CTA_N;

    float* e0s = (float*)dynsmem;             // [64][132]
    for (int idx = tid; idx < CTA_M * CTA_N; idx += 256) {
        const int r = idx >> 7, cc = idx & 127;
        e0s[r * 132 + cc] = g_e0[(size_t)(b0 + r) * 512 + i0 + cc];
    }
    float* sred = (float*)(dynsmem + CTA_M * 132 * 4);   // [64][4]
    __syncthreads();

    const int colq = (lane & 3) * 2;          // this lane's col pair base
    #pragma unroll
    for (int mi = 0; mi < 2; ++mi) {
        #pragma unroll
        for (int half = 0; half < 2; ++half) {
            const int rl = warpM * 32 + mi * 16 + half * 8 + (lane >> 2);
            float s = 0.0f;
            #pragma unroll
            for (int nf = 0; nf < 4; ++nf) {
                const int cc = warpN * 32 + nf * 8 + colq;
                s = fmaf(acc[mi][nf][half * 2 + 0], e0s[rl * 132 + cc],     s);
                s = fmaf(acc[mi][nf][half * 2 + 1], e0s[rl * 132 + cc + 1], s);
            }
            s += __shfl_xor_sync(0xFFFFFFFFu, s, 1);
            s += __shfl_xor_sync(0xFFFFFFFFu, s, 2);
            if ((lane & 3) == 0) sred[rl * 4 + warpN] = s;
        }
    }
    __syncthreads();

    if (tid < CTA_M) {
        const int b = b0 + tid;
        float s = sred[tid * 4] + sred[tid * 4 + 1] + sred[tid * 4 + 2] + sred[tid * 4 + 3];
        const float xf = (kmat == 0) ? x[2 * b] : (kmat == 1) ? x[2 * b + 1] : 1.0f;
        g_part[(size_t)b * NPART + ks * NT + nt] = s * xf;
    }
}

// ---------------------------------------------------------------------------
// Kernel 3: deterministic final sum + normalization.
// ---------------------------------------------------------------------------
__global__ void __launch_bounds__(B_SZ) final_kernel(float* __restrict__ out)
{
    const int b = threadIdx.x;
    float s = 0.0f;
    #pragma unroll
    for (int p = 0; p < NPART; ++p) s += g_part[b * NPART + p];
    out[b] = s / g_S[b];
}

// ---------------------------------------------------------------------------
extern "C" void kernel_launch(void* const* d_in, const int* in_sizes, int n_in,
                              void* d_out, int out_size)
{
    const float* x     = (const float*)d_in[0];   // [B, 2]
    const float* mean  = (const float*)d_in[1];   // [2, M]
    const float* sigma = (const float*)d_in[2];   // [2, M]
    const float* cw    = (const float*)d_in[3];   // [R, 2]
    const float* cb    = (const float*)d_in[4];   // [R, 1]
    float* out = (float*)d_out;                   // [B, 1]

    cudaFuncSetAttribute(gemm_kernel, cudaFuncAttributeMaxDynamicSharedMemorySize, DSMEM_BYTES);

    prep_kernel<<<384, 512>>>(x, mean, sigma, cw, cb);
    gemm_kernel<<<dim3(MT, NT, KS), 256, DSMEM_BYTES>>>(x);
    final_kernel<<<1, B_SZ>>>(out);
}

// round 10
// speedup vs baseline: 2.9201x; 1.2549x over previous
#include <cuda_runtime.h>
#include <cuda_bf16.h>
#include <cstdint>

// ANFIS on GB300 — round 9: HMMA with fused precision passes + on-the-fly
// fp32->bf16(hi,lo) weight split. No materialized bf16 weight copies.
//
//   e0[b,i], e1[b,j] raw memberships; S[b] = (sum e0)(sum e1)
//   D[b, n] = sum_j e1[b,j] * W[n,j]
//   N-tiles: nt<8  -> cols 0-63 = cw0 rows (x0 weight), 64-127 = cw1 (x1)
//            nt>=8 -> 128 cb rows (weight 1)
//   out[b] = sum_n e0-weighted D / S[b]
// Precision: per chunk, acc += ah*Wh + al*Wh + ah*Wl (all fp32 accum).

#define M_MF 512
#define B_SZ 256
#define CTA_M 64
#define CTA_N 128
#define KCH  64
#define KPAD 72
#define MT 4
#define NT 12
#define KS 2
#define NPART (NT * KS)              // 24
#define NCHUNK ((M_MF / KS) / KCH)   // 4
#define A_ELEMS (128 * KPAD)         // eh rows 0-63, el rows 64-127
#define B_ELEMS (256 * KPAD)         // Wh rows 0-127, Wl rows 128-255
#define STAGE_BYTES ((A_ELEMS + B_ELEMS) * 2)   // 55296
#define DSMEM_BYTES (2 * STAGE_BYTES)           // 110592

__device__ __align__(16) __nv_bfloat16 g_e1h[B_SZ * M_MF];
__device__ __align__(16) __nv_bfloat16 g_e1l[B_SZ * M_MF];
__device__ __align__(16) float g_e0[B_SZ * M_MF];
__device__ float g_S[B_SZ];
__device__ float g_part[B_SZ * NPART];

__device__ __forceinline__ uint32_t smem_u32(const void* p) {
    uint32_t a;
    asm("{ .reg .u64 t; cvta.to.shared.u64 t, %1; cvt.u32.u64 %0, t; }" : "=r"(a) : "l"(p));
    return a;
}
__device__ __forceinline__ void ldsm_x4(uint32_t& r0, uint32_t& r1, uint32_t& r2,
                                        uint32_t& r3, uint32_t addr) {
    asm volatile("ldmatrix.sync.aligned.m8n8.x4.shared.b16 {%0,%1,%2,%3}, [%4];"
                 : "=r"(r0), "=r"(r1), "=r"(r2), "=r"(r3) : "r"(addr));
}
__device__ __forceinline__ void mma16816(float* d, const uint32_t* a,
                                         uint32_t b0, uint32_t b1) {
    asm volatile(
        "mma.sync.aligned.m16n8k16.row.col.f32.bf16.bf16.f32 "
        "{%0,%1,%2,%3}, {%4,%5,%6,%7}, {%8,%9}, {%0,%1,%2,%3};"
        : "+f"(d[0]), "+f"(d[1]), "+f"(d[2]), "+f"(d[3])
        : "r"(a[0]), "r"(a[1]), "r"(a[2]), "r"(a[3]), "r"(b0), "r"(b1));
}

// ---------------------------------------------------------------------------
// Kernel 1 (prep): membership only. 128 blocks x 512 threads, 2 batches/block.
// ---------------------------------------------------------------------------
__global__ void __launch_bounds__(512) prep_kernel(
    const float* __restrict__ x,
    const float* __restrict__ mean,
    const float* __restrict__ sigma)
{
    __shared__ float sm[16][4];
    const int m    = threadIdx.x;
    const int lane = m & 31;
    const int wrp  = m >> 5;
    const int ba   = 2 * blockIdx.x, bb = ba + 1;

    const float i0s = __fdividef(1.0f, sigma[m]);
    const float i1s = __fdividef(1.0f, sigma[512 + m]);
    const float mn0 = mean[m], mn1 = mean[512 + m];
    const float xa0 = x[2 * ba], xa1 = x[2 * ba + 1];
    const float xb0 = x[2 * bb], xb1 = x[2 * bb + 1];

    float d;
    d = (xa0 - mn0) * i0s;  const float e0a = __expf(-d * d);
    d = (xa1 - mn1) * i1s;  const float e1a = __expf(-d * d);
    d = (xb0 - mn0) * i0s;  const float e0b = __expf(-d * d);
    d = (xb1 - mn1) * i1s;  const float e1b = __expf(-d * d);

    float r0 = e0a, r1 = e1a, r2 = e0b, r3 = e1b;
    #pragma unroll
    for (int off = 16; off > 0; off >>= 1) {
        r0 += __shfl_down_sync(0xFFFFFFFFu, r0, off);
        r1 += __shfl_down_sync(0xFFFFFFFFu, r1, off);
        r2 += __shfl_down_sync(0xFFFFFFFFu, r2, off);
        r3 += __shfl_down_sync(0xFFFFFFFFu, r3, off);
    }
    if (lane == 0) { sm[wrp][0] = r0; sm[wrp][1] = r1; sm[wrp][2] = r2; sm[wrp][3] = r3; }
    __syncthreads();
    if (m < 32) {
        float v0 = (lane < 16) ? sm[lane][0] : 0.0f;
        float v1 = (lane < 16) ? sm[lane][1] : 0.0f;
        float v2 = (lane < 16) ? sm[lane][2] : 0.0f;
        float v3 = (lane < 16) ? sm[lane][3] : 0.0f;
        #pragma unroll
        for (int off = 8; off > 0; off >>= 1) {
            v0 += __shfl_down_sync(0xFFFFFFFFu, v0, off);
            v1 += __shfl_down_sync(0xFFFFFFFFu, v1, off);
            v2 += __shfl_down_sync(0xFFFFFFFFu, v2, off);
            v3 += __shfl_down_sync(0xFFFFFFFFu, v3, off);
        }
        if (lane == 0) { g_S[ba] = v0 * v1; g_S[bb] = v2 * v3; }
    }

    g_e0[(size_t)ba * 512 + m] = e0a;
    g_e0[(size_t)bb * 512 + m] = e0b;
    __nv_bfloat16 h;
    h = __float2bfloat16(e1a);
    g_e1h[(size_t)ba * 512 + m] = h;
    g_e1l[(size_t)ba * 512 + m] = __float2bfloat16(e1a - __bfloat162float(h));
    h = __float2bfloat16(e1b);
    g_e1h[(size_t)bb * 512 + m] = h;
    g_e1l[(size_t)bb * 512 + m] = __float2bfloat16(e1b - __bfloat162float(h));
}

// ---------------------------------------------------------------------------
// Kernel 2: HMMA GEMM, fused 3-product chunks. Grid (4, 12, 2), 256 threads.
// CTA tile 64(b) x 128(n); warps 2(m) x 4(n), warp tile 32x32.
// ---------------------------------------------------------------------------
extern __shared__ __align__(16) char dynsmem[];

__global__ void __launch_bounds__(256) gemm_kernel(
    const float* __restrict__ x,
    const float* __restrict__ cw,
    const float* __restrict__ cb)
{
    const int tid   = threadIdx.x;
    const int lane  = tid & 31;
    const int wid   = tid >> 5;
    const int warpM = wid >> 2;          // 0..1
    const int warpN = wid & 3;           // 0..3
    const int mt = blockIdx.x, nt = blockIdx.y, ks = blockIdx.z;
    const int b0 = mt * CTA_M;
    const bool tile_cw = (nt < 8);
    const int i0g = tile_cw ? nt * 64 : (nt - 8) * 128;
    const int jbase = ks * (M_MF / KS);

    __nv_bfloat16* bufA[2] = { (__nv_bfloat16*)dynsmem,
                               (__nv_bfloat16*)(dynsmem + STAGE_BYTES) };
    __nv_bfloat16* bufB[2] = { bufA[0] + A_ELEMS, bufA[1] + A_ELEMS };

    float acc[2][4][4];
    #pragma unroll
    for (int mi = 0; mi < 2; ++mi)
        #pragma unroll
        for (int nf = 0; nf < 4; ++nf)
            #pragma unroll
            for (int e = 0; e < 4; ++e) acc[mi][nf][e] = 0.0f;

    uint4  ra[4];       // e1h / e1l bf16
    float4 rb[8];       // fp32 weights

    auto ldg_chunk = [&](int c) {
        const int j0 = jbase + c * KCH;
        #pragma unroll
        for (int it = 0; it < 4; ++it) {
            const int idx = tid + it * 256;
            const int mat = idx >> 9;
            const int rem = idx & 511;
            const int r = rem >> 3, c8 = (rem & 7) * 8;
            const __nv_bfloat16* src = (mat ? g_e1l : g_e1h)
                                     + (size_t)(b0 + r) * 512 + j0 + c8;
            ra[it] = *(const uint4*)src;
        }
        if (tile_cw) {
            #pragma unroll
            for (int it = 0; it < 8; ++it) {
                const int idx = tid + it * 256;
                const int r = idx >> 5, jq = (idx & 31) * 2;
                rb[it] = *(const float4*)(cw + ((size_t)(i0g + r) * 512 + j0 + jq) * 2);
            }
        } else {
            #pragma unroll
            for (int it = 0; it < 8; ++it) {
                const int idx = tid + it * 256;
                const int r = idx >> 4, jq = (idx & 15) * 4;
                rb[it] = *(const float4*)(cb + (size_t)(i0g + r) * 512 + j0 + jq);
            }
        }
    };

    auto sts_chunk = [&](int buf) {
        __nv_bfloat16* Ab = bufA[buf];
        __nv_bfloat16* Bb = bufB[buf];
        #pragma unroll
        for (int it = 0; it < 4; ++it) {
            const int idx = tid + it * 256;
            const int mat = idx >> 9;
            const int rem = idx & 511;
            const int r = rem >> 3, c8 = (rem & 7) * 8;
            *(uint4*)&Ab[(mat * 64 + r) * KPAD + c8] = ra[it];
        }
        if (tile_cw) {
            #pragma unroll
            for (int it = 0; it < 8; ++it) {
                const int idx = tid + it * 256;
                const int r = idx >> 5, jq = (idx & 31) * 2;
                const float4 v = rb[it];
                // v = {cw0[j], cw1[j], cw0[j+1], cw1[j+1]}
                __nv_bfloat162 h0 = __floats2bfloat162_rn(v.x, v.z);
                __nv_bfloat162 h1 = __floats2bfloat162_rn(v.y, v.w);
                __nv_bfloat162 l0 = __floats2bfloat162_rn(
                    v.x - __bfloat162float(h0.x), v.z - __bfloat162float(h0.y));
                __nv_bfloat162 l1 = __floats2bfloat162_rn(
                    v.y - __bfloat162float(h1.x), v.w - __bfloat162float(h1.y));
                *(__nv_bfloat162*)&Bb[(r      ) * KPAD + jq] = h0;  // cw0 hi
                *(__nv_bfloat162*)&Bb[(r +  64) * KPAD + jq] = h1;  // cw1 hi
                *(__nv_bfloat162*)&Bb[(r + 128) * KPAD + jq] = l0;  // cw0 lo
                *(__nv_bfloat162*)&Bb[(r + 192) * KPAD + jq] = l1;  // cw1 lo
            }
        } else {
            #pragma unroll
            for (int it = 0; it < 8; ++it) {
                const int idx = tid + it * 256;
                const int r = idx >> 4, jq = (idx & 15) * 4;
                const float4 v = rb[it];
                __nv_bfloat162 ha = __floats2bfloat162_rn(v.x, v.y);
                __nv_bfloat162 hb = __floats2bfloat162_rn(v.z, v.w);
                __nv_bfloat162 la = __floats2bfloat162_rn(
                    v.x - __bfloat162float(ha.x), v.y - __bfloat162float(ha.y));
                __nv_bfloat162 lb = __floats2bfloat162_rn(
                    v.z - __bfloat162float(hb.x), v.w - __bfloat162float(hb.y));
                *(__nv_bfloat162*)&Bb[(r      ) * KPAD + jq]     = ha;
                *(__nv_bfloat162*)&Bb[(r      ) * KPAD + jq + 2] = hb;
                *(__nv_bfloat162*)&Bb[(r + 128) * KPAD + jq]     = la;
                *(__nv_bfloat162*)&Bb[(r + 128) * KPAD + jq + 2] = lb;
            }
        }
    };

    // ldmatrix lane address components (validated mapping from R8)
    const int aRow = warpM * 32 + (lane & 15);
    const int aCol = (lane >> 4) << 3;
    const int bRow = warpN * 32 + ((lane >> 4) << 3) + (lane & 7);
    const int bCol = ((lane >> 3) & 1) << 3;

    ldg_chunk(0);
    sts_chunk(0);
    __syncthreads();

    for (int c = 0; c < NCHUNK; ++c) {
        const int cur = c & 1;
        if (c + 1 < NCHUNK) ldg_chunk(c + 1);

        const uint32_t sA = smem_u32(bufA[cur]);
        const uint32_t sB = smem_u32(bufB[cur]);
        #pragma unroll
        for (int k16 = 0; k16 < KCH / 16; ++k16) {
            const int k0 = k16 * 16;
            uint32_t ah[2][4], al[2][4];
            #pragma unroll
            for (int mi = 0; mi < 2; ++mi) {
                ldsm_x4(ah[mi][0], ah[mi][1], ah[mi][2], ah[mi][3],
                        sA + (uint32_t)(((aRow + mi * 16) * KPAD + k0 + aCol) * 2));
                ldsm_x4(al[mi][0], al[mi][1], al[mi][2], al[mi][3],
                        sA + (uint32_t)(((aRow + mi * 16 + 64) * KPAD + k0 + aCol) * 2));
            }
            uint32_t bh[4][2], bl[4][2];
            #pragma unroll
            for (int bi = 0; bi < 2; ++bi) {
                uint32_t r0, r1, r2, r3;
                ldsm_x4(r0, r1, r2, r3,
                        sB + (uint32_t)(((bRow + bi * 16) * KPAD + k0 + bCol) * 2));
                bh[bi * 2][0] = r0; bh[bi * 2][1] = r1;
                bh[bi * 2 + 1][0] = r2; bh[bi * 2 + 1][1] = r3;
                ldsm_x4(r0, r1, r2, r3,
                        sB + (uint32_t)(((bRow + bi * 16 + 128) * KPAD + k0 + bCol) * 2));
                bl[bi * 2][0] = r0; bl[bi * 2][1] = r1;
                bl[bi * 2 + 1][0] = r2; bl[bi * 2 + 1][1] = r3;
            }
            #pragma unroll
            for (int mi = 0; mi < 2; ++mi)
                #pragma unroll
                for (int nf = 0; nf < 4; ++nf) {
                    mma16816(acc[mi][nf], ah[mi], bh[nf][0], bh[nf][1]);
                    mma16816(acc[mi][nf], al[mi], bh[nf][0], bh[nf][1]);
                    mma16816(acc[mi][nf], ah[mi], bl[nf][0], bl[nf][1]);
                }
        }

        if (c + 1 < NCHUNK) sts_chunk(cur ^ 1);
        __syncthreads();
    }

    // ---- epilogue ----
    const int EP = tile_cw ? 68 : 132;
    const int EC = tile_cw ? 64 : 128;
    float* e0s  = (float*)dynsmem;
    float* xs   = e0s + 64 * 132;      // [64][2]
    float* sred = xs + 128;            // [64][4]

    for (int idx = tid; idx < 64 * EC; idx += 256) {
        const int r = tile_cw ? (idx >> 6) : (idx >> 7);
        const int c = idx & (EC - 1);
        e0s[r * EP + c] = g_e0[(size_t)(b0 + r) * 512 + i0g + c];
    }
    if (tid < 128) xs[tid] = x[b0 * 2 + tid];
    __syncthreads();

    const int colq = (lane & 3) * 2;
    #pragma unroll
    for (int mi = 0; mi < 2; ++mi) {
        #pragma unroll
        for (int half = 0; half < 2; ++half) {
            const int rl = warpM * 32 + mi * 16 + half * 8 + (lane >> 2);
            float s = 0.0f;
            #pragma unroll
            for (int nf = 0; nf < 4; ++nf) {
                const int ce = (tile_cw ? (warpN & 1) * 32 : warpN * 32) + nf * 8 + colq;
                s = fmaf(acc[mi][nf][half * 2 + 0], e0s[rl * EP + ce],     s);
                s = fmaf(acc[mi][nf][half * 2 + 1], e0s[rl * EP + ce + 1], s);
            }
            s += __shfl_xor_sync(0xFFFFFFFFu, s, 1);
            s += __shfl_xor_sync(0xFFFFFFFFu, s, 2);
            if ((lane & 3) == 0) {
                const float xf = tile_cw ? xs[rl * 2 + (warpN >> 1)] : 1.0f;
                sred[rl * 4 + warpN] = s * xf;
            }
        }
    }
    __syncthreads();

    if (tid < CTA_M) {
        const int b = b0 + tid;
        const float s = sred[tid * 4] + sred[tid * 4 + 1]
                      + sred[tid * 4 + 2] + sred[tid * 4 + 3];
        g_part[(size_t)b * NPART + ks * NT + nt] = s;
    }
}

// ---------------------------------------------------------------------------
// Kernel 3: deterministic final sum + normalization.
// ---------------------------------------------------------------------------
__global__ void __launch_bounds__(B_SZ) final_kernel(float* __restrict__ out)
{
    const int b = threadIdx.x;
    float s = 0.0f;
    #pragma unroll
    for (int p = 0; p < NPART; ++p) s += g_part[b * NPART + p];
    out[b] = s / g_S[b];
}

// ---------------------------------------------------------------------------
extern "C" void kernel_launch(void* const* d_in, const int* in_sizes, int n_in,
                              void* d_out, int out_size)
{
    const float* x     = (const float*)d_in[0];   // [B, 2]
    const float* mean  = (const float*)d_in[1];   // [2, M]
    const float* sigma = (const float*)d_in[2];   // [2, M]
    const float* cw    = (const float*)d_in[3];   // [R, 2]
    const float* cb    = (const float*)d_in[4];   // [R, 1]
    float* out = (float*)d_out;                   // [B, 1]

    cudaFuncSetAttribute(gemm_kernel, cudaFuncAttributeMaxDynamicSharedMemorySize, DSMEM_BYTES);

    prep_kernel<<<128, 512>>>(x, mean, sigma);
    gemm_kernel<<<dim3(MT, NT, KS), 256, DSMEM_BYTES>>>(x, cw, cb);
    final_kernel<<<1, B_SZ>>>(out);
}

// round 15
// speedup vs baseline: 2.9512x; 1.0107x over previous
#include <cuda_runtime.h>
#include <cuda_bf16.h>
#include <cstdint>

// ANFIS on GB300 — round 10: single fused persistent kernel.
// Phase 0: memberships (batch b -> CTA b%96) + S[b]   [inline, was prep_kernel]
// global spin barrier (96 CTAs, all co-resident: 1 CTA/SM, 96 < 148 SMs)
// Phase 1: HMMA GEMM, fused bf16 hi/lo precision passes (validated R9)
// Phase 2: partials + arrival counter; last CTA does deterministic final sum.

#define M_MF 512
#define B_SZ 256
#define CTA_M 64
#define CTA_N 128
#define KCH  64
#define KPAD 72
#define MT 4
#define NT 12
#define KS 2
#define NCTA (MT * NT * KS)          // 96
#define NPART (NT * KS)              // 24
#define NCHUNK ((M_MF / KS) / KCH)   // 4
#define A_ELEMS (128 * KPAD)
#define B_ELEMS (256 * KPAD)
#define STAGE_BYTES ((A_ELEMS + B_ELEMS) * 2)   // 55296
#define DSMEM_BYTES (2 * STAGE_BYTES)           // 110592

__device__ __align__(16) __nv_bfloat16 g_e1h[B_SZ * M_MF];
__device__ __align__(16) __nv_bfloat16 g_e1l[B_SZ * M_MF];
__device__ __align__(16) float g_e0[B_SZ * M_MF];
__device__ float g_S[B_SZ];
__device__ float g_part[B_SZ * NPART];
__device__ int g_bar1;
__device__ int g_bar2;

__device__ __forceinline__ uint32_t smem_u32(const void* p) {
    uint32_t a;
    asm("{ .reg .u64 t; cvta.to.shared.u64 t, %1; cvt.u32.u64 %0, t; }" : "=r"(a) : "l"(p));
    return a;
}
__device__ __forceinline__ void ldsm_x4(uint32_t& r0, uint32_t& r1, uint32_t& r2,
                                        uint32_t& r3, uint32_t addr) {
    asm volatile("ldmatrix.sync.aligned.m8n8.x4.shared.b16 {%0,%1,%2,%3}, [%4];"
                 : "=r"(r0), "=r"(r1), "=r"(r2), "=r"(r3) : "r"(addr));
}
__device__ __forceinline__ void mma16816(float* d, const uint32_t* a,
                                         uint32_t b0, uint32_t b1) {
    asm volatile(
        "mma.sync.aligned.m16n8k16.row.col.f32.bf16.bf16.f32 "
        "{%0,%1,%2,%3}, {%4,%5,%6,%7}, {%8,%9}, {%0,%1,%2,%3};"
        : "+f"(d[0]), "+f"(d[1]), "+f"(d[2]), "+f"(d[3])
        : "r"(a[0]), "r"(a[1]), "r"(a[2]), "r"(a[3]), "r"(b0), "r"(b1));
}

extern __shared__ __align__(16) char dynsmem[];

__global__ void __launch_bounds__(256) fused_kernel(
    const float* __restrict__ x,
    const float* __restrict__ mean,
    const float* __restrict__ sigma,
    const float* __restrict__ cw,
    const float* __restrict__ cb,
    float* __restrict__ out)
{
    const int tid   = threadIdx.x;
    const int lane  = tid & 31;
    const int wid   = tid >> 5;
    const int ctaid = blockIdx.x + MT * (blockIdx.y + NT * blockIdx.z);

    __shared__ float s_red[8][2];
    __shared__ int   s_last;

    // ===================== Phase 0: memberships =====================
    {
        const int m  = tid;         // and m+256
        const float mn0a = mean[m],        sg0a = sigma[m];
        const float mn1a = mean[512 + m],  sg1a = sigma[512 + m];
        const float mn0c = mean[m + 256],       sg0c = sigma[m + 256];
        const float mn1c = mean[512 + m + 256], sg1c = sigma[512 + m + 256];
        const float i0a = __fdividef(1.0f, sg0a), i1a = __fdividef(1.0f, sg1a);
        const float i0c = __fdividef(1.0f, sg0c), i1c = __fdividef(1.0f, sg1c);

        for (int b = ctaid; b < B_SZ; b += NCTA) {
            const float x0 = x[2 * b], x1 = x[2 * b + 1];
            float d;
            d = (x0 - mn0a) * i0a;  const float e0a = __expf(-d * d);
            d = (x1 - mn1a) * i1a;  const float e1a = __expf(-d * d);
            d = (x0 - mn0c) * i0c;  const float e0c = __expf(-d * d);
            d = (x1 - mn1c) * i1c;  const float e1c = __expf(-d * d);

            const size_t o = (size_t)b * 512 + m;
            g_e0[o]       = e0a;
            g_e0[o + 256] = e0c;
            __nv_bfloat16 h;
            h = __float2bfloat16(e1a);
            g_e1h[o] = h;  g_e1l[o] = __float2bfloat16(e1a - __bfloat162float(h));
            h = __float2bfloat16(e1c);
            g_e1h[o + 256] = h;  g_e1l[o + 256] = __float2bfloat16(e1c - __bfloat162float(h));

            float p0 = e0a + e0c, p1 = e1a + e1c;
            #pragma unroll
            for (int off = 16; off > 0; off >>= 1) {
                p0 += __shfl_down_sync(0xFFFFFFFFu, p0, off);
                p1 += __shfl_down_sync(0xFFFFFFFFu, p1, off);
            }
            if (lane == 0) { s_red[wid][0] = p0; s_red[wid][1] = p1; }
            __syncthreads();
            if (tid == 0) {
                float s0 = 0.0f, s1 = 0.0f;
                #pragma unroll
                for (int w = 0; w < 8; ++w) { s0 += s_red[w][0]; s1 += s_red[w][1]; }
                g_S[b] = s0 * s1;
            }
            __syncthreads();
        }
    }

    // ===================== global barrier =====================
    if (tid == 0) {
        __threadfence();
        atomicAdd(&g_bar1, 1);
        while (*(volatile int*)&g_bar1 < NCTA) { }
        __threadfence();
    }
    __syncthreads();

    // ===================== Phase 1: GEMM =====================
    const int warpM = wid >> 2;
    const int warpN = wid & 3;
    const int mt = blockIdx.x, nt = blockIdx.y, ks = blockIdx.z;
    const int b0 = mt * CTA_M;
    const bool tile_cw = (nt < 8);
    const int i0g = tile_cw ? nt * 64 : (nt - 8) * 128;
    const int jbase = ks * (M_MF / KS);

    __nv_bfloat16* bufA[2] = { (__nv_bfloat16*)dynsmem,
                               (__nv_bfloat16*)(dynsmem + STAGE_BYTES) };
    __nv_bfloat16* bufB[2] = { bufA[0] + A_ELEMS, bufA[1] + A_ELEMS };

    float acc[2][4][4];
    #pragma unroll
    for (int mi = 0; mi < 2; ++mi)
        #pragma unroll
        for (int nf = 0; nf < 4; ++nf)
            #pragma unroll
            for (int e = 0; e < 4; ++e) acc[mi][nf][e] = 0.0f;

    uint4  ra[4];
    float4 rb[8];

    auto ldg_chunk = [&](int c) {
        const int j0 = jbase + c * KCH;
        #pragma unroll
        for (int it = 0; it < 4; ++it) {
            const int idx = tid + it * 256;
            const int mat = idx >> 9;
            const int rem = idx & 511;
            const int r = rem >> 3, c8 = (rem & 7) * 8;
            const __nv_bfloat16* src = (mat ? g_e1l : g_e1h)
                                     + (size_t)(b0 + r) * 512 + j0 + c8;
            ra[it] = *(const uint4*)src;
        }
        if (tile_cw) {
            #pragma unroll
            for (int it = 0; it < 8; ++it) {
                const int idx = tid + it * 256;
                const int r = idx >> 5, jq = (idx & 31) * 2;
                rb[it] = *(const float4*)(cw + ((size_t)(i0g + r) * 512 + j0 + jq) * 2);
            }
        } else {
            #pragma unroll
            for (int it = 0; it < 8; ++it) {
                const int idx = tid + it * 256;
                const int r = idx >> 4, jq = (idx & 15) * 4;
                rb[it] = *(const float4*)(cb + (size_t)(i0g + r) * 512 + j0 + jq);
            }
        }
    };

    auto sts_chunk = [&](int buf) {
        __nv_bfloat16* Ab = bufA[buf];
        __nv_bfloat16* Bb = bufB[buf];
        #pragma unroll
        for (int it = 0; it < 4; ++it) {
            const int idx = tid + it * 256;
            const int mat = idx >> 9;
            const int rem = idx & 511;
            const int r = rem >> 3, c8 = (rem & 7) * 8;
            *(uint4*)&Ab[(mat * 64 + r) * KPAD + c8] = ra[it];
        }
        if (tile_cw) {
            #pragma unroll
            for (int it = 0; it < 8; ++it) {
                const int idx = tid + it * 256;
                const int r = idx >> 5, jq = (idx & 31) * 2;
                const float4 v = rb[it];
                __nv_bfloat162 h0 = __floats2bfloat162_rn(v.x, v.z);
                __nv_bfloat162 h1 = __floats2bfloat162_rn(v.y, v.w);
                __nv_bfloat162 l0 = __floats2bfloat162_rn(
                    v.x - __bfloat162float(h0.x), v.z - __bfloat162float(h0.y));
                __nv_bfloat162 l1 = __floats2bfloat162_rn(
                    v.y - __bfloat162float(h1.x), v.w - __bfloat162float(h1.y));
                *(__nv_bfloat162*)&Bb[(r      ) * KPAD + jq] = h0;
                *(__nv_bfloat162*)&Bb[(r +  64) * KPAD + jq] = h1;
                *(__nv_bfloat162*)&Bb[(r + 128) * KPAD + jq] = l0;
                *(__nv_bfloat162*)&Bb[(r + 192) * KPAD + jq] = l1;
            }
        } else {
            #pragma unroll
            for (int it = 0; it < 8; ++it) {
                const int idx = tid + it * 256;
                const int r = idx >> 4, jq = (idx & 15) * 4;
                const float4 v = rb[it];
                __nv_bfloat162 ha = __floats2bfloat162_rn(v.x, v.y);
                __nv_bfloat162 hb = __floats2bfloat162_rn(v.z, v.w);
                __nv_bfloat162 la = __floats2bfloat162_rn(
                    v.x - __bfloat162float(ha.x), v.y - __bfloat162float(ha.y));
                __nv_bfloat162 lb = __floats2bfloat162_rn(
                    v.z - __bfloat162float(hb.x), v.w - __bfloat162float(hb.y));
                *(__nv_bfloat162*)&Bb[(r      ) * KPAD + jq]     = ha;
                *(__nv_bfloat162*)&Bb[(r      ) * KPAD + jq + 2] = hb;
                *(__nv_bfloat162*)&Bb[(r + 128) * KPAD + jq]     = la;
                *(__nv_bfloat162*)&Bb[(r + 128) * KPAD + jq + 2] = lb;
            }
        }
    };

    const int aRow = warpM * 32 + (lane & 15);
    const int aCol = (lane >> 4) << 3;
    const int bRow = warpN * 32 + ((lane >> 4) << 3) + (lane & 7);
    const int bCol = ((lane >> 3) & 1) << 3;

    ldg_chunk(0);
    sts_chunk(0);
    __syncthreads();

    for (int c = 0; c < NCHUNK; ++c) {
        const int cur = c & 1;
        if (c + 1 < NCHUNK) ldg_chunk(c + 1);

        const uint32_t sA = smem_u32(bufA[cur]);
        const uint32_t sB = smem_u32(bufB[cur]);
        #pragma unroll
        for (int k16 = 0; k16 < KCH / 16; ++k16) {
            const int k0 = k16 * 16;
            uint32_t ah[2][4], al[2][4];
            #pragma unroll
            for (int mi = 0; mi < 2; ++mi) {
                ldsm_x4(ah[mi][0], ah[mi][1], ah[mi][2], ah[mi][3],
                        sA + (uint32_t)(((aRow + mi * 16) * KPAD + k0 + aCol) * 2));
                ldsm_x4(al[mi][0], al[mi][1], al[mi][2], al[mi][3],
                        sA + (uint32_t)(((aRow + mi * 16 + 64) * KPAD + k0 + aCol) * 2));
            }
            uint32_t bh[4][2], bl[4][2];
            #pragma unroll
            for (int bi = 0; bi < 2; ++bi) {
                uint32_t r0, r1, r2, r3;
                ldsm_x4(r0, r1, r2, r3,
                        sB + (uint32_t)(((bRow + bi * 16) * KPAD + k0 + bCol) * 2));
                bh[bi * 2][0] = r0; bh[bi * 2][1] = r1;
                bh[bi * 2 + 1][0] = r2; bh[bi * 2 + 1][1] = r3;
                ldsm_x4(r0, r1, r2, r3,
                        sB + (uint32_t)(((bRow + bi * 16 + 128) * KPAD + k0 + bCol) * 2));
                bl[bi * 2][0] = r0; bl[bi * 2][1] = r1;
                bl[bi * 2 + 1][0] = r2; bl[bi * 2 + 1][1] = r3;
            }
            #pragma unroll
            for (int mi = 0; mi < 2; ++mi)
                #pragma unroll
                for (int nf = 0; nf < 4; ++nf) {
                    mma16816(acc[mi][nf], ah[mi], bh[nf][0], bh[nf][1]);
                    mma16816(acc[mi][nf], al[mi], bh[nf][0], bh[nf][1]);
                    mma16816(acc[mi][nf], ah[mi], bl[nf][0], bl[nf][1]);
                }
        }

        if (c + 1 < NCHUNK) sts_chunk(cur ^ 1);
        __syncthreads();
    }

    // ===================== Phase 2: epilogue + final =====================
    const int EP = tile_cw ? 68 : 132;
    const int EC = tile_cw ? 64 : 128;
    float* e0s  = (float*)dynsmem;
    float* xs   = e0s + 64 * 132;
    float* sred = xs + 128;

    for (int idx = tid; idx < 64 * EC; idx += 256) {
        const int r = tile_cw ? (idx >> 6) : (idx >> 7);
        const int c = idx & (EC - 1);
        e0s[r * EP + c] = g_e0[(size_t)(b0 + r) * 512 + i0g + c];
    }
    if (tid < 128) xs[tid] = x[b0 * 2 + tid];
    __syncthreads();

    const int colq = (lane & 3) * 2;
    #pragma unroll
    for (int mi = 0; mi < 2; ++mi) {
        #pragma unroll
        for (int half = 0; half < 2; ++half) {
            const int rl = warpM * 32 + mi * 16 + half * 8 + (lane >> 2);
            float s = 0.0f;
            #pragma unroll
            for (int nf = 0; nf < 4; ++nf) {
                const int ce = (tile_cw ? (warpN & 1) * 32 : warpN * 32) + nf * 8 + colq;
                s = fmaf(acc[mi][nf][half * 2 + 0], e0s[rl * EP + ce],     s);
                s = fmaf(acc[mi][nf][half * 2 + 1], e0s[rl * EP + ce + 1], s);
            }
            s += __shfl_xor_sync(0xFFFFFFFFu, s, 1);
            s += __shfl_xor_sync(0xFFFFFFFFu, s, 2);
            if ((lane & 3) == 0) {
                const float xf = tile_cw ? xs[rl * 2 + (warpN >> 1)] : 1.0f;
                sred[rl * 4 + warpN] = s * xf;
            }
        }
    }
    __syncthreads();

    if (tid < CTA_M) {
        const int b = b0 + tid;
        const float s = sred[tid * 4] + sred[tid * 4 + 1]
                      + sred[tid * 4 + 2] + sred[tid * 4 + 3];
        g_part[(size_t)b * NPART + ks * NT + nt] = s;
    }
    __syncthreads();

    if (tid == 0) {
        __threadfence();
        const int old = atomicAdd(&g_bar2, 1);
        s_last = (old == NCTA - 1);
    }
    __syncthreads();

    if (s_last) {
        __threadfence();   // threadFenceReduction pattern: partials now visible
        const int b = tid; // 256 threads, 256 batches
        float s = 0.0f;
        #pragma unroll
        for (int p = 0; p < NPART; ++p) s += g_part[(size_t)b * NPART + p];
        out[b] = s / g_S[b];
        if (tid == 0) { g_bar1 = 0; g_bar2 = 0; }
    }
}

// ---------------------------------------------------------------------------
extern "C" void kernel_launch(void* const* d_in, const int* in_sizes, int n_in,
                              void* d_out, int out_size)
{
    const float* x     = (const float*)d_in[0];   // [B, 2]
    const float* mean  = (const float*)d_in[1];   // [2, M]
    const float* sigma = (const float*)d_in[2];   // [2, M]
    const float* cw    = (const float*)d_in[3];   // [R, 2]
    const float* cb    = (const float*)d_in[4];   // [R, 1]
    float* out = (float*)d_out;                   // [B, 1]

    cudaFuncSetAttribute(fused_kernel, cudaFuncAttributeMaxDynamicSharedMemorySize, DSMEM_BYTES);
    fused_kernel<<<dim3(MT, NT, KS), 256, DSMEM_BYTES>>>(x, mean, sigma, cw, cb, out);
}

// round 16
// speedup vs baseline: 3.0109x; 1.0202x over previous
#include <cuda_runtime.h>
#include <cuda_bf16.h>
#include <cstdint>

// ANFIS on GB300 — round 11: fused persistent kernel, latency-optimized.
//   512 threads/CTA (16 warps), sync-free membership (1 warp per batch),
//   weight prefetch before the global barrier.
// Phase 0: memberships, warp-per-batch, no block syncs
// global spin barrier (96 CTAs all co-resident; 1 CTA/SM, 96 < 148)
// Phase 1: HMMA GEMM, fused bf16 hi/lo precision passes
// Phase 2: partials; last CTA does deterministic final sum.

#define M_MF 512
#define B_SZ 256
#define CTA_M 64
#define CTA_N 128
#define KCH  64
#define KPAD 72
#define MT 4
#define NT 12
#define KS 2
#define NCTA (MT * NT * KS)          // 96
#define NPART (NT * KS)              // 24
#define NCHUNK ((M_MF / KS) / KCH)   // 4
#define NTHR 512
#define A_ELEMS (128 * KPAD)
#define B_ELEMS (256 * KPAD)
#define STAGE_BYTES ((A_ELEMS + B_ELEMS) * 2)   // 55296
#define DSMEM_BYTES (2 * STAGE_BYTES)           // 110592

__device__ __align__(16) __nv_bfloat16 g_e1h[B_SZ * M_MF];
__device__ __align__(16) __nv_bfloat16 g_e1l[B_SZ * M_MF];
__device__ __align__(16) float g_e0[B_SZ * M_MF];
__device__ float g_S[B_SZ];
__device__ float g_part[B_SZ * NPART];
__device__ int g_bar1;
__device__ int g_bar2;

__device__ __forceinline__ uint32_t smem_u32(const void* p) {
    uint32_t a;
    asm("{ .reg .u64 t; cvta.to.shared.u64 t, %1; cvt.u32.u64 %0, t; }" : "=r"(a) : "l"(p));
    return a;
}
__device__ __forceinline__ void ldsm_x4(uint32_t& r0, uint32_t& r1, uint32_t& r2,
                                        uint32_t& r3, uint32_t addr) {
    asm volatile("ldmatrix.sync.aligned.m8n8.x4.shared.b16 {%0,%1,%2,%3}, [%4];"
                 : "=r"(r0), "=r"(r1), "=r"(r2), "=r"(r3) : "r"(addr));
}
__device__ __forceinline__ void mma16816(float* d, const uint32_t* a,
                                         uint32_t b0, uint32_t b1) {
    asm volatile(
        "mma.sync.aligned.m16n8k16.row.col.f32.bf16.bf16.f32 "
        "{%0,%1,%2,%3}, {%4,%5,%6,%7}, {%8,%9}, {%0,%1,%2,%3};"
        : "+f"(d[0]), "+f"(d[1]), "+f"(d[2]), "+f"(d[3])
        : "r"(a[0]), "r"(a[1]), "r"(a[2]), "r"(a[3]), "r"(b0), "r"(b1));
}

extern __shared__ __align__(16) char dynsmem[];

__global__ void __launch_bounds__(NTHR, 1) fused_kernel(
    const float* __restrict__ x,
    const float* __restrict__ mean,
    const float* __restrict__ sigma,
    const float* __restrict__ cw,
    const float* __restrict__ cb,
    float* __restrict__ out)
{
    const int tid   = threadIdx.x;
    const int lane  = tid & 31;
    const int wid   = tid >> 5;
    const int ctaid = blockIdx.x + MT * (blockIdx.y + NT * blockIdx.z);

    __shared__ int s_last;

    const int mt = blockIdx.x, nt = blockIdx.y, ks = blockIdx.z;
    const int b0 = mt * CTA_M;
    const bool tile_cw = (nt < 8);
    const int i0g = tile_cw ? nt * 64 : (nt - 8) * 128;
    const int jbase = ks * (M_MF / KS);

    __nv_bfloat16* bufA[2] = { (__nv_bfloat16*)dynsmem,
                               (__nv_bfloat16*)(dynsmem + STAGE_BYTES) };
    __nv_bfloat16* bufB[2] = { bufA[0] + A_ELEMS, bufA[1] + A_ELEMS };

    uint4  ra[2];       // e1h / e1l bf16
    float4 rb[4];       // fp32 weights

    auto ldg_w = [&](int c) {
        const int j0 = jbase + c * KCH;
        if (tile_cw) {
            #pragma unroll
            for (int it = 0; it < 4; ++it) {
                const int idx = tid + it * NTHR;
                const int r = idx >> 5, jq = (idx & 31) * 2;
                rb[it] = *(const float4*)(cw + ((size_t)(i0g + r) * 512 + j0 + jq) * 2);
            }
        } else {
            #pragma unroll
            for (int it = 0; it < 4; ++it) {
                const int idx = tid + it * NTHR;
                const int r = idx >> 4, jq = (idx & 15) * 4;
                rb[it] = *(const float4*)(cb + (size_t)(i0g + r) * 512 + j0 + jq);
            }
        }
    };
    auto sts_w = [&](int buf) {
        __nv_bfloat16* Bb = bufB[buf];
        if (tile_cw) {
            #pragma unroll
            for (int it = 0; it < 4; ++it) {
                const int idx = tid + it * NTHR;
                const int r = idx >> 5, jq = (idx & 31) * 2;
                const float4 v = rb[it];
                __nv_bfloat162 h0 = __floats2bfloat162_rn(v.x, v.z);
                __nv_bfloat162 h1 = __floats2bfloat162_rn(v.y, v.w);
                __nv_bfloat162 l0 = __floats2bfloat162_rn(
                    v.x - __bfloat162float(h0.x), v.z - __bfloat162float(h0.y));
                __nv_bfloat162 l1 = __floats2bfloat162_rn(
                    v.y - __bfloat162float(h1.x), v.w - __bfloat162float(h1.y));
                *(__nv_bfloat162*)&Bb[(r      ) * KPAD + jq] = h0;  // cw0 hi
                *(__nv_bfloat162*)&Bb[(r +  64) * KPAD + jq] = h1;  // cw1 hi
                *(__nv_bfloat162*)&Bb[(r + 128) * KPAD + jq] = l0;  // cw0 lo
                *(__nv_bfloat162*)&Bb[(r + 192) * KPAD + jq] = l1;  // cw1 lo
            }
        } else {
            #pragma unroll
            for (int it = 0; it < 4; ++it) {
                const int idx = tid + it * NTHR;
                const int r = idx >> 4, jq = (idx & 15) * 4;
                const float4 v = rb[it];
                __nv_bfloat162 ha = __floats2bfloat162_rn(v.x, v.y);
                __nv_bfloat162 hb = __floats2bfloat162_rn(v.z, v.w);
                __nv_bfloat162 la = __floats2bfloat162_rn(
                    v.x - __bfloat162float(ha.x), v.y - __bfloat162float(ha.y));
                __nv_bfloat162 lb = __floats2bfloat162_rn(
                    v.z - __bfloat162float(hb.x), v.w - __bfloat162float(hb.y));
                *(__nv_bfloat162*)&Bb[(r      ) * KPAD + jq]     = ha;
                *(__nv_bfloat162*)&Bb[(r      ) * KPAD + jq + 2] = hb;
                *(__nv_bfloat162*)&Bb[(r + 128) * KPAD + jq]     = la;
                *(__nv_bfloat162*)&Bb[(r + 128) * KPAD + jq + 2] = lb;
            }
        }
    };
    auto ldg_a = [&](int c) {
        const int j0 = jbase + c * KCH;
        #pragma unroll
        for (int it = 0; it < 2; ++it) {
            const int idx = tid + it * NTHR;
            const int mat = idx >> 9;
            const int rem = idx & 511;
            const int r = rem >> 3, c8 = (rem & 7) * 8;
            const __nv_bfloat16* src = (mat ? g_e1l : g_e1h)
                                     + (size_t)(b0 + r) * 512 + j0 + c8;
            ra[it] = *(const uint4*)src;
        }
    };
    auto sts_a = [&](int buf) {
        __nv_bfloat16* Ab = bufA[buf];
        #pragma unroll
        for (int it = 0; it < 2; ++it) {
            const int idx = tid + it * NTHR;
            const int mat = idx >> 9;
            const int rem = idx & 511;
            const int r = rem >> 3, c8 = (rem & 7) * 8;
            *(uint4*)&Ab[(mat * 64 + r) * KPAD + c8] = ra[it];
        }
    };

    // ============ Weight prefetch (independent of phase 0) ============
    ldg_w(0);
    sts_w(0);

    // ============ Phase 0: memberships, 1 warp per batch ============
    {
        const int gw = wid * NCTA + ctaid;          // 0..1535, spread across CTAs
        if (gw < B_SZ) {
            const int b = gw;
            const float x0 = x[2 * b], x1 = x[2 * b + 1];
            float s0 = 0.0f, s1 = 0.0f;
            #pragma unroll
            for (int k = 0; k < 16; ++k) {
                const int m = k * 32 + lane;
                float d0 = (x0 - mean[m]) * __fdividef(1.0f, sigma[m]);
                const float e0 = __expf(-d0 * d0);
                float d1 = (x1 - mean[512 + m]) * __fdividef(1.0f, sigma[512 + m]);
                const float e1 = __expf(-d1 * d1);
                const size_t o = (size_t)b * 512 + m;
                g_e0[o] = e0;
                const __nv_bfloat16 h = __float2bfloat16(e1);
                g_e1h[o] = h;
                g_e1l[o] = __float2bfloat16(e1 - __bfloat162float(h));
                s0 += e0;  s1 += e1;
            }
            #pragma unroll
            for (int off = 16; off > 0; off >>= 1) {
                s0 += __shfl_down_sync(0xFFFFFFFFu, s0, off);
                s1 += __shfl_down_sync(0xFFFFFFFFu, s1, off);
            }
            if (lane == 0) g_S[b] = s0 * s1;
        }
    }

    // ============ global barrier ============
    __syncthreads();                   // all warps done with phase 0 + sts_w(0)
    if (tid == 0) {
        __threadfence();
        atomicAdd(&g_bar1, 1);
        while (*(volatile int*)&g_bar1 < NCTA) { }
        __threadfence();
    }
    __syncthreads();

    // ============ Phase 1: GEMM (16 warps, warp tile 16m x 32n) ============
    const int warpM = wid >> 2;        // 0..3
    const int warpN = wid & 3;         // 0..3

    float acc[4][4];
    #pragma unroll
    for (int nf = 0; nf < 4; ++nf)
        #pragma unroll
        for (int e = 0; e < 4; ++e) acc[nf][e] = 0.0f;

    const int aRow = warpM * 16 + (lane & 15);
    const int aCol = (lane >> 4) << 3;
    const int bRow = warpN * 32 + ((lane >> 4) << 3) + (lane & 7);
    const int bCol = ((lane >> 3) & 1) << 3;

    ldg_a(0);
    sts_a(0);
    __syncthreads();

    for (int c = 0; c < NCHUNK; ++c) {
        const int cur = c & 1;
        if (c + 1 < NCHUNK) { ldg_w(c + 1); ldg_a(c + 1); }

        const uint32_t sA = smem_u32(bufA[cur]);
        const uint32_t sB = smem_u32(bufB[cur]);
        #pragma unroll
        for (int k16 = 0; k16 < KCH / 16; ++k16) {
            const int k0 = k16 * 16;
            uint32_t ah[4], al[4];
            ldsm_x4(ah[0], ah[1], ah[2], ah[3],
                    sA + (uint32_t)((aRow * KPAD + k0 + aCol) * 2));
            ldsm_x4(al[0], al[1], al[2], al[3],
                    sA + (uint32_t)(((aRow + 64) * KPAD + k0 + aCol) * 2));
            uint32_t bh[4][2], bl[4][2];
            #pragma unroll
            for (int bi = 0; bi < 2; ++bi) {
                uint32_t r0, r1, r2, r3;
                ldsm_x4(r0, r1, r2, r3,
                        sB + (uint32_t)(((bRow + bi * 16) * KPAD + k0 + bCol) * 2));
                bh[bi * 2][0] = r0; bh[bi * 2][1] = r1;
                bh[bi * 2 + 1][0] = r2; bh[bi * 2 + 1][1] = r3;
                ldsm_x4(r0, r1, r2, r3,
                        sB + (uint32_t)(((bRow + bi * 16 + 128) * KPAD + k0 + bCol) * 2));
                bl[bi * 2][0] = r0; bl[bi * 2][1] = r1;
                bl[bi * 2 + 1][0] = r2; bl[bi * 2 + 1][1] = r3;
            }
            #pragma unroll
            for (int nf = 0; nf < 4; ++nf) {
                mma16816(acc[nf], ah, bh[nf][0], bh[nf][1]);
                mma16816(acc[nf], al, bh[nf][0], bh[nf][1]);
                mma16816(acc[nf], ah, bl[nf][0], bl[nf][1]);
            }
        }

        if (c + 1 < NCHUNK) { sts_w(cur ^ 1); sts_a(cur ^ 1); }
        __syncthreads();
    }

    // ============ Phase 2: epilogue + final ============
    const int EP = tile_cw ? 68 : 132;
    const int EC = tile_cw ? 64 : 128;
    float* e0s  = (float*)dynsmem;
    float* xs   = e0s + 64 * 132;
    float* sred = xs + 128;

    for (int idx = tid; idx < 64 * EC; idx += NTHR) {
        const int r = tile_cw ? (idx >> 6) : (idx >> 7);
        const int c = idx & (EC - 1);
        e0s[r * EP + c] = g_e0[(size_t)(b0 + r) * 512 + i0g + c];
    }
    if (tid < 128) xs[tid] = x[b0 * 2 + tid];
    __syncthreads();

    const int colq = (lane & 3) * 2;
    #pragma unroll
    for (int half = 0; half < 2; ++half) {
        const int rl = warpM * 16 + half * 8 + (lane >> 2);
        float s = 0.0f;
        #pragma unroll
        for (int nf = 0; nf < 4; ++nf) {
            const int ce = (tile_cw ? (warpN & 1) * 32 : warpN * 32) + nf * 8 + colq;
            s = fmaf(acc[nf][half * 2 + 0], e0s[rl * EP + ce],     s);
            s = fmaf(acc[nf][half * 2 + 1], e0s[rl * EP + ce + 1], s);
        }
        s += __shfl_xor_sync(0xFFFFFFFFu, s, 1);
        s += __shfl_xor_sync(0xFFFFFFFFu, s, 2);
        if ((lane & 3) == 0) {
            const float xf = tile_cw ? xs[rl * 2 + (warpN >> 1)] : 1.0f;
            sred[rl * 4 + warpN] = s * xf;
        }
    }
    __syncthreads();

    if (tid < CTA_M) {
        const int b = b0 + tid;
        const float s = sred[tid * 4] + sred[tid * 4 + 1]
                      + sred[tid * 4 + 2] + sred[tid * 4 + 3];
        g_part[(size_t)b * NPART + ks * NT + nt] = s;
    }
    __syncthreads();

    if (tid == 0) {
        __threadfence();
        const int old = atomicAdd(&g_bar2, 1);
        s_last = (old == NCTA - 1);
    }
    __syncthreads();

    if (s_last) {
        __threadfence();
        if (tid < B_SZ) {
            const int b = tid;
            float s = 0.0f;
            #pragma unroll
            for (int p = 0; p < NPART; ++p) s += g_part[(size_t)b * NPART + p];
            out[b] = s / g_S[b];
        }
        if (tid == 0) { g_bar1 = 0; g_bar2 = 0; }
    }
}

// ---------------------------------------------------------------------------
extern "C" void kernel_launch(void* const* d_in, const int* in_sizes, int n_in,
                              void* d_out, int out_size)
{
    const float* x     = (const float*)d_in[0];   // [B, 2]
    const float* mean  = (const float*)d_in[1];   // [2, M]
    const float* sigma = (const float*)d_in[2];   // [2, M]
    const float* cw    = (const float*)d_in[3];   // [R, 2]
    const float* cb    = (const float*)d_in[4];   // [R, 1]
    float* out = (float*)d_out;                   // [B, 1]

    cudaFuncSetAttribute(fused_kernel, cudaFuncAttributeMaxDynamicSharedMemorySize, DSMEM_BYTES);
    fused_kernel<<<dim3(MT, NT, KS), NTHR, DSMEM_BYTES>>>(x, mean, sigma, cw, cb, out);
}

// round 17
// speedup vs baseline: 3.0585x; 1.0158x over previous
#include <cuda_runtime.h>
#include <cuda_bf16.h>
#include <cstdint>

// ANFIS on GB300 — round 12: fully local fused kernel. Each CTA recomputes the
// memberships it needs directly into SMEM (A operand + epilogue e0), removing
// the cross-CTA phase-0 barrier and all e0/e1 gmem round-trips. Normalizer S
// is assembled from per-CTA partials by the last-arriving CTA.

#define M_MF 512
#define B_SZ 256
#define CTA_M 64
#define CTA_N 128
#define KCH  64
#define KPAD 72
#define A_STRIDE 264                 // 256 local j + 8 pad (bf16)
#define MT 4
#define NT 12
#define KS 2
#define NCTA (MT * NT * KS)          // 96
#define NP_GEMM (NT * KS)            // 24
#define NP_TOT  (NP_GEMM + 4 + 2)    // + 4 S0 partials + 2 S1 partials = 30
#define NCHUNK ((M_MF / KS) / KCH)   // 4
#define NTHR 512

#define OFF_A    0
#define A_BYTES  (128 * A_STRIDE * 2)            // 67584 (eh rows 0-63, el 64-127)
#define OFF_B0   A_BYTES
#define B_BYTES  (256 * KPAD * 2)                // 36864
#define OFF_B1   (OFF_B0 + B_BYTES)
#define OFF_E0S  (OFF_B1 + B_BYTES)              // 141312
#define E0S_BYTES (64 * 132 * 4)                 // 33792
#define OFF_XS   (OFF_E0S + E0S_BYTES)           // 175104
#define OFF_SRED (OFF_XS + 512)                  // 175616
#define DSMEM_BYTES (OFF_SRED + 64 * 4 * 4)      // 176640

__device__ float g_part[B_SZ * NP_TOT];
__device__ int g_bar;

__device__ __forceinline__ uint32_t smem_u32(const void* p) {
    uint32_t a;
    asm("{ .reg .u64 t; cvta.to.shared.u64 t, %1; cvt.u32.u64 %0, t; }" : "=r"(a) : "l"(p));
    return a;
}
__device__ __forceinline__ void ldsm_x4(uint32_t& r0, uint32_t& r1, uint32_t& r2,
                                        uint32_t& r3, uint32_t addr) {
    asm volatile("ldmatrix.sync.aligned.m8n8.x4.shared.b16 {%0,%1,%2,%3}, [%4];"
                 : "=r"(r0), "=r"(r1), "=r"(r2), "=r"(r3) : "r"(addr));
}
__device__ __forceinline__ void mma16816(float* d, const uint32_t* a,
                                         uint32_t b0, uint32_t b1) {
    asm volatile(
        "mma.sync.aligned.m16n8k16.row.col.f32.bf16.bf16.f32 "
        "{%0,%1,%2,%3}, {%4,%5,%6,%7}, {%8,%9}, {%0,%1,%2,%3};"
        : "+f"(d[0]), "+f"(d[1]), "+f"(d[2]), "+f"(d[3])
        : "r"(a[0]), "r"(a[1]), "r"(a[2]), "r"(a[3]), "r"(b0), "r"(b1));
}

extern __shared__ __align__(16) char dynsmem[];

__global__ void __launch_bounds__(NTHR, 1) fused_kernel(
    const float* __restrict__ x,
    const float* __restrict__ mean,
    const float* __restrict__ sigma,
    const float* __restrict__ cw,
    const float* __restrict__ cb,
    float* __restrict__ out)
{
    const int tid   = threadIdx.x;
    const int lane  = tid & 31;
    const int wid   = tid >> 5;

    __shared__ int s_last;

    const int mt = blockIdx.x, nt = blockIdx.y, ks = blockIdx.z;
    const int b0 = mt * CTA_M;
    const bool tile_cw = (nt < 8);
    const int i0g = tile_cw ? nt * 64 : (nt - 8) * 128;
    const int jbase = ks * (M_MF / KS);

    __nv_bfloat16* Ab    = (__nv_bfloat16*)(dynsmem + OFF_A);
    __nv_bfloat16* bufB[2] = { (__nv_bfloat16*)(dynsmem + OFF_B0),
                               (__nv_bfloat16*)(dynsmem + OFF_B1) };
    float* e0s  = (float*)(dynsmem + OFF_E0S);   // [64][EP]
    float* xs   = (float*)(dynsmem + OFF_XS);    // [128]
    float* sred = (float*)(dynsmem + OFF_SRED);  // [64][4]

    float4 rb[4];   // fp32 weight staging

    auto ldg_w = [&](int c) {
        const int j0 = jbase + c * KCH;
        if (tile_cw) {
            #pragma unroll
            for (int it = 0; it < 4; ++it) {
                const int idx = tid + it * NTHR;
                const int r = idx >> 5, jq = (idx & 31) * 2;
                rb[it] = *(const float4*)(cw + ((size_t)(i0g + r) * 512 + j0 + jq) * 2);
            }
        } else {
            #pragma unroll
            for (int it = 0; it < 4; ++it) {
                const int idx = tid + it * NTHR;
                const int r = idx >> 4, jq = (idx & 15) * 4;
                rb[it] = *(const float4*)(cb + (size_t)(i0g + r) * 512 + j0 + jq);
            }
        }
    };
    auto sts_w = [&](int buf) {
        __nv_bfloat16* Bb = bufB[buf];
        if (tile_cw) {
            #pragma unroll
            for (int it = 0; it < 4; ++it) {
                const int idx = tid + it * NTHR;
                const int r = idx >> 5, jq = (idx & 31) * 2;
                const float4 v = rb[it];
                __nv_bfloat162 h0 = __floats2bfloat162_rn(v.x, v.z);
                __nv_bfloat162 h1 = __floats2bfloat162_rn(v.y, v.w);
                __nv_bfloat162 l0 = __floats2bfloat162_rn(
                    v.x - __bfloat162float(h0.x), v.z - __bfloat162float(h0.y));
                __nv_bfloat162 l1 = __floats2bfloat162_rn(
                    v.y - __bfloat162float(h1.x), v.w - __bfloat162float(h1.y));
                *(__nv_bfloat162*)&Bb[(r      ) * KPAD + jq] = h0;  // cw0 hi
                *(__nv_bfloat162*)&Bb[(r +  64) * KPAD + jq] = h1;  // cw1 hi
                *(__nv_bfloat162*)&Bb[(r + 128) * KPAD + jq] = l0;  // cw0 lo
                *(__nv_bfloat162*)&Bb[(r + 192) * KPAD + jq] = l1;  // cw1 lo
            }
        } else {
            #pragma unroll
            for (int it = 0; it < 4; ++it) {
                const int idx = tid + it * NTHR;
                const int r = idx >> 4, jq = (idx & 15) * 4;
                const float4 v = rb[it];
                __nv_bfloat162 ha = __floats2bfloat162_rn(v.x, v.y);
                __nv_bfloat162 hb = __floats2bfloat162_rn(v.z, v.w);
                __nv_bfloat162 la = __floats2bfloat162_rn(
                    v.x - __bfloat162float(ha.x), v.y - __bfloat162float(ha.y));
                __nv_bfloat162 lb = __floats2bfloat162_rn(
                    v.z - __bfloat162float(hb.x), v.w - __bfloat162float(hb.y));
                *(__nv_bfloat162*)&Bb[(r      ) * KPAD + jq]     = ha;
                *(__nv_bfloat162*)&Bb[(r      ) * KPAD + jq + 2] = hb;
                *(__nv_bfloat162*)&Bb[(r + 128) * KPAD + jq]     = la;
                *(__nv_bfloat162*)&Bb[(r + 128) * KPAD + jq + 2] = lb;
            }
        }
    };

    // ---- kernel start: weight prefetch (DRAM) + stage x, fully parallel ----
    ldg_w(0);
    if (tid < 128) xs[tid] = x[b0 * 2 + tid];
    __syncthreads();

    // ---- local memberships: e1 -> A operand (bf16 hi/lo), e0 -> e0s ----
    {
        const int jloc = tid & 255;
        const int bgrp = tid >> 8;           // 0..1 -> 32 batches each
        const int j = jbase + jloc;
        const float mn1 = mean[512 + j];
        const float is1 = __fdividef(1.0f, sigma[512 + j]);
        #pragma unroll 4
        for (int k = 0; k < 32; ++k) {
            const int bl = bgrp * 32 + k;
            const float d = (xs[2 * bl + 1] - mn1) * is1;
            const float e1 = __expf(-d * d);
            const __nv_bfloat16 h = __float2bfloat16(e1);
            Ab[bl * A_STRIDE + jloc] = h;
            Ab[(bl + 64) * A_STRIDE + jloc] =
                __float2bfloat16(e1 - __bfloat162float(h));
        }
    }
    {
        const int EC = tile_cw ? 64 : 128;
        const int EP = tile_cw ? 68 : 132;
        const int ic  = tid & (EC - 1);
        const int grp = tile_cw ? (tid >> 6) : (tid >> 7);
        const int nb  = 64 / (NTHR / EC);    // 8 or 16
        const int i = i0g + ic;
        const float mn0 = mean[i];
        const float is0 = __fdividef(1.0f, sigma[i]);
        #pragma unroll 4
        for (int k = 0; k < nb; ++k) {
            const int bl = grp * nb + k;
            const float d = (xs[2 * bl] - mn0) * is0;
            e0s[bl * EP + ic] = __expf(-d * d);
        }
    }
    sts_w(0);
    __syncthreads();

    // ---- mainloop: B double-buffered, A resident for all chunks ----
    const int warpM = wid >> 2;
    const int warpN = wid & 3;
    float acc[4][4];
    #pragma unroll
    for (int nf = 0; nf < 4; ++nf)
        #pragma unroll
        for (int e = 0; e < 4; ++e) acc[nf][e] = 0.0f;

    const int aRow = warpM * 16 + (lane & 15);
    const int aColL = (lane >> 4) << 3;
    const int bRow = warpN * 32 + ((lane >> 4) << 3) + (lane & 7);
    const int bCol = ((lane >> 3) & 1) << 3;
    const uint32_t sA = smem_u32(Ab);

    for (int c = 0; c < NCHUNK; ++c) {
        const int cur = c & 1;
        if (c + 1 < NCHUNK) ldg_w(c + 1);

        const uint32_t sB = smem_u32(bufB[cur]);
        #pragma unroll
        for (int k16 = 0; k16 < KCH / 16; ++k16) {
            const int k0 = k16 * 16;
            const int ac = c * KCH + k0 + aColL;
            uint32_t ah[4], al[4];
            ldsm_x4(ah[0], ah[1], ah[2], ah[3],
                    sA + (uint32_t)((aRow * A_STRIDE + ac) * 2));
            ldsm_x4(al[0], al[1], al[2], al[3],
                    sA + (uint32_t)(((aRow + 64) * A_STRIDE + ac) * 2));
            uint32_t bh[4][2], bl[4][2];
            #pragma unroll
            for (int bi = 0; bi < 2; ++bi) {
                uint32_t r0, r1, r2, r3;
                ldsm_x4(r0, r1, r2, r3,
                        sB + (uint32_t)(((bRow + bi * 16) * KPAD + k0 + bCol) * 2));
                bh[bi * 2][0] = r0; bh[bi * 2][1] = r1;
                bh[bi * 2 + 1][0] = r2; bh[bi * 2 + 1][1] = r3;
                ldsm_x4(r0, r1, r2, r3,
                        sB + (uint32_t)(((bRow + bi * 16 + 128) * KPAD + k0 + bCol) * 2));
                bl[bi * 2][0] = r0; bl[bi * 2][1] = r1;
                bl[bi * 2 + 1][0] = r2; bl[bi * 2 + 1][1] = r3;
            }
            #pragma unroll
            for (int nf = 0; nf < 4; ++nf) {
                mma16816(acc[nf], ah, bh[nf][0], bh[nf][1]);
                mma16816(acc[nf], al, bh[nf][0], bh[nf][1]);
                mma16816(acc[nf], ah, bl[nf][0], bl[nf][1]);
            }
        }

        if (c + 1 < NCHUNK) { __syncthreads(); sts_w(cur ^ 1); __syncthreads(); }
    }

    // ---- epilogue: combine with e0 (already in smem) ----
    const int EP = tile_cw ? 68 : 132;
    const int colq = (lane & 3) * 2;
    #pragma unroll
    for (int half = 0; half < 2; ++half) {
        const int rl = warpM * 16 + half * 8 + (lane >> 2);
        float s = 0.0f;
        #pragma unroll
        for (int nf = 0; nf < 4; ++nf) {
            const int ce = (tile_cw ? (warpN & 1) * 32 : warpN * 32) + nf * 8 + colq;
            s = fmaf(acc[nf][half * 2 + 0], e0s[rl * EP + ce],     s);
            s = fmaf(acc[nf][half * 2 + 1], e0s[rl * EP + ce + 1], s);
        }
        s += __shfl_xor_sync(0xFFFFFFFFu, s, 1);
        s += __shfl_xor_sync(0xFFFFFFFFu, s, 2);
        if ((lane & 3) == 0) {
            const float xf = tile_cw ? xs[rl * 2 + (warpN >> 1)] : 1.0f;
            sred[rl * 4 + warpN] = s * xf;
        }
    }
    __syncthreads();

    if (tid < CTA_M) {
        const int b = b0 + tid;
        const float s = sred[tid * 4] + sred[tid * 4 + 1]
                      + sred[tid * 4 + 2] + sred[tid * 4 + 3];
        g_part[(size_t)b * NP_TOT + ks * NT + nt] = s;
    }

    // ---- normalizer partials ----
    if (!tile_cw && ks == 0) {
        // S0 partial: sum e0 over this CTA's 128 i-values (fixed order)
        if (tid < 64) {
            float s0 = 0.0f;
            #pragma unroll 8
            for (int c = 0; c < 128; ++c) s0 += e0s[tid * 132 + c];
            g_part[(size_t)(b0 + tid) * NP_TOT + NP_GEMM + (nt - 8)] = s0;
        }
    }
    if (nt == 0) {
        // S1 partial: sum (eh+el) over this CTA's 256 j-values from A smem
        const int bl = tid >> 3;             // 0..63
        const int sl = tid & 7;              // 32-j slice
        float s1 = 0.0f;
        #pragma unroll 8
        for (int jc = sl * 32; jc < sl * 32 + 32; ++jc)
            s1 += __bfloat162float(Ab[bl * A_STRIDE + jc])
                + __bfloat162float(Ab[(bl + 64) * A_STRIDE + jc]);
        s1 += __shfl_xor_sync(0xFFFFFFFFu, s1, 1);
        s1 += __shfl_xor_sync(0xFFFFFFFFu, s1, 2);
        s1 += __shfl_xor_sync(0xFFFFFFFFu, s1, 4);
        if (sl == 0)
            g_part[(size_t)(b0 + bl) * NP_TOT + NP_GEMM + 4 + ks] = s1;
    }
    __syncthreads();

    // ---- arrival barrier; last CTA reduces ----
    if (tid == 0) {
        __threadfence();
        const int old = atomicAdd(&g_bar, 1);
        s_last = (old == NCTA - 1);
    }
    __syncthreads();

    if (s_last) {
        __threadfence();
        if (tid < B_SZ) {
            const float* p = &g_part[(size_t)tid * NP_TOT];
            float s = 0.0f;
            #pragma unroll
            for (int q = 0; q < NP_GEMM; ++q) s += p[q];
            const float S0 = p[24] + p[25] + p[26] + p[27];
            const float S1 = p[28] + p[29];
            out[tid] = s / (S0 * S1);
        }
        if (tid == 0) g_bar = 0;
    }
}

// ---------------------------------------------------------------------------
extern "C" void kernel_launch(void* const* d_in, const int* in_sizes, int n_in,
                              void* d_out, int out_size)
{
    const float* x     = (const float*)d_in[0];   // [B, 2]
    const float* mean  = (const float*)d_in[1];   // [2, M]
    const float* sigma = (const float*)d_in[2];   // [2, M]
    const float* cw    = (const float*)d_in[3];   // [R, 2]
    const float* cb    = (const float*)d_in[4];   // [R, 1]
    float* out = (float*)d_out;                   // [B, 1]

    cudaFuncSetAttribute(fused_kernel, cudaFuncAttributeMaxDynamicSharedMemorySize, DSMEM_BYTES);
    fused_kernel<<<dim3(MT, NT, KS), NTHR, DSMEM_BYTES>>>(x, mean, sigma, cw, cb, out);
}